// round 1
// baseline (speedup 1.0000x reference)
#include <cuda_runtime.h>

#define BB 8
#define NV 207
#define CC 2
#define TT 12
#define EE 64
#define NHEADS 4
#define DKH 16
#define LL 2
#define FFE 256
#define TOUTV 12
#define NGH 8
#define ALPHA 0.2f
#define NEGV (-9.0e15f)
#define NN (NV*NV)

// scratch: out buffer (B,N,T,E)
__device__ float g_out[BB*NV*TT*EE];

__device__ __forceinline__ float warp_sum(float v){
  #pragma unroll
  for (int o=16;o;o>>=1) v += __shfl_xor_sync(0xffffffffu, v, o);
  return v;
}

// ---------------------------------------------------------------------------
// K1: GAT (8 heads, online softmax) + conv1, fused.
// grid (96, 52), block 128. One warp per (bt, i) row.
// ---------------------------------------------------------------------------
__global__ void __launch_bounds__(128) k_gat(
    const float* __restrict__ x,      // (B,C,N,T)
    const int*   __restrict__ adj,    // (B,N,N)
    const float* __restrict__ W2,     // (8,4,2)
    const float* __restrict__ ga,     // (8,2)
    const float* __restrict__ gb,     // (8,2)
    const float* __restrict__ w1,     // (4,64)
    const float* __restrict__ b1)     // (64)
{
  __shared__ float2 xbs[NV];
  __shared__ float  w1s[4*64];
  __shared__ float  b1s[64];
  int bt = blockIdx.x;
  int b = bt / TT, t = bt % TT;
  int tid = threadIdx.x;
  for (int idx = tid; idx < NV; idx += 128) {
    float v0 = x[((b*2+0)*NV + idx)*TT + t];
    float v1 = x[((b*2+1)*NV + idx)*TT + t];
    xbs[idx] = make_float2(v0, v1);
  }
  for (int idx = tid; idx < 256; idx += 128) w1s[idx] = w1[idx];
  if (tid < 64) b1s[tid] = b1[tid];
  __syncthreads();

  int warp = tid >> 5, lane = tid & 31;
  int i = blockIdx.y * 4 + warp;
  if (i >= NV) return;

  // GAT weights into registers (uniform across lanes)
  float w2r[NGH][4][2];
  float ar[NGH][2];
  #pragma unroll
  for (int h=0;h<NGH;h++){
    #pragma unroll
    for (int k=0;k<4;k++){
      w2r[h][k][0]=W2[(h*4+k)*2+0];
      w2r[h][k][1]=W2[(h*4+k)*2+1];
    }
    ar[h][0]=ga[h*2]; ar[h][1]=ga[h*2+1];
  }

  float m[NGH], d[NGH], n0[NGH], n1[NGH];
  #pragma unroll
  for (int h=0;h<NGH;h++){ m[h]=NEGV; d[h]=0.f; n0[h]=0.f; n1[h]=0.f; }

  const int* arow = adj + (b*NV + i)*NV;
  for (int j = lane; j < NV; j += 32) {
    bool ok = arow[j] > 0;
    // replicate the reference's scrambled comb reshape exactly:
    // comb[bt,i,j,k] with r = 2*(i*N+j) + k//C
    int r0 = 2*(i*NV + j);
    int r1 = r0 + 1;
    int a0 = (r0 < NN) ? (r0 / NV) : ((r0 - NN) % NV);
    int a1 = (r1 < NN) ? (r1 / NV) : ((r1 - NN) % NV);
    float2 ca = xbs[a0];
    float2 cb = xbs[a1];
    float2 xj = xbs[j];
    #pragma unroll
    for (int h=0;h<NGH;h++){
      float we0 = ca.x*w2r[h][0][0] + ca.y*w2r[h][1][0] + cb.x*w2r[h][2][0] + cb.y*w2r[h][3][0];
      float we1 = ca.x*w2r[h][0][1] + ca.y*w2r[h][1][1] + cb.x*w2r[h][2][1] + cb.y*w2r[h][3][1];
      we0 = (we0 > 0.f) ? we0 : ALPHA*we0;
      we1 = (we1 > 0.f) ? we1 : ALPHA*we1;
      float e = we0*ar[h][0] + we1*ar[h][1];
      e = ok ? e : NEGV;
      float mn = fmaxf(m[h], e);
      float s  = __expf(m[h]-mn);
      float w  = __expf(e-mn);
      d[h]  = d[h]*s  + w;
      n0[h] = n0[h]*s + w*xj.x;
      n1[h] = n1[h]*s + w*xj.y;
      m[h]  = mn;
    }
  }
  // butterfly combine across lanes
  #pragma unroll
  for (int off=16; off; off>>=1){
    #pragma unroll
    for (int h=0;h<NGH;h++){
      float m2 = __shfl_xor_sync(0xffffffffu, m[h], off);
      float d2 = __shfl_xor_sync(0xffffffffu, d[h], off);
      float p2 = __shfl_xor_sync(0xffffffffu, n0[h], off);
      float q2 = __shfl_xor_sync(0xffffffffu, n1[h], off);
      float mn = fmaxf(m[h], m2);
      float s1 = __expf(m[h]-mn), s2 = __expf(m2-mn);
      d[h]  = d[h]*s1  + d2*s2;
      n0[h] = n0[h]*s1 + p2*s2;
      n1[h] = n1[h]*s1 + q2*s2;
      m[h]  = mn;
    }
  }
  float acc0=0.f, acc1=0.f;
  #pragma unroll
  for (int h=0;h<NGH;h++){
    float inv = 1.0f/d[h];
    acc0 += tanhf(n0[h]*inv + gb[h*2+0]);
    acc1 += tanhf(n1[h]*inv + gb[h*2+1]);
  }
  acc0 *= 0.125f; acc1 *= 0.125f;

  // fused conv1: xcat channels = [x0, x1, gat0, gat1]
  float2 xi = xbs[i];
  long obase = ((long)(b*NV + i)*TT + t)*EE;
  #pragma unroll
  for (int r=0;r<2;r++){
    int e = lane + r*32;
    g_out[obase + e] = xi.x*w1s[e] + xi.y*w1s[64+e]
                     + acc0*w1s[128+e] + acc1*w1s[192+e] + b1s[e];
  }
}

// ---------------------------------------------------------------------------
// LayerNorm over 64 elems/row, rows t = warp, warp+8 (12 rows, 8 warps)
// ---------------------------------------------------------------------------
__device__ __forceinline__ void ln_rows(const float* __restrict__ buf,
                                        const float* __restrict__ g,
                                        const float* __restrict__ bb,
                                        float* __restrict__ dst){
  int warp = threadIdx.x>>5, lane = threadIdx.x&31;
  for (int t = warp; t < 12; t += 8){
    float v0 = buf[t*64+lane], v1 = buf[t*64+lane+32];
    float s  = warp_sum(v0+v1);
    float s2 = warp_sum(v0*v0+v1*v1);
    float mean = s*(1.f/64.f);
    float var  = s2*(1.f/64.f) - mean*mean;
    float r = rsqrtf(var + 1e-5f);
    dst[t*64+lane]    = (v0-mean)*r*g[lane]    + bb[lane];
    dst[t*64+lane+32] = (v1-mean)*r*g[lane+32] + bb[lane+32];
  }
}

// ---------------------------------------------------------------------------
// K2: one transformer block layer. grid 1656 (= B*N), block 256.
// ---------------------------------------------------------------------------
__global__ void __launch_bounds__(256) k_layer(
    const float* __restrict__ temb,
    const float* __restrict__ Wq, const float* __restrict__ Wk,
    const float* __restrict__ Wv, const float* __restrict__ Wo,
    const float* __restrict__ bo,
    const float* __restrict__ ln1g, const float* __restrict__ ln1b,
    const float* __restrict__ ln2g, const float* __restrict__ ln2b,
    const float* __restrict__ fw1, const float* __restrict__ fb1,
    const float* __restrict__ fw2, const float* __restrict__ fb2,
    const float* __restrict__ lng, const float* __restrict__ lnb,
    int l)
{
  __shared__ float sT[768], sQQ[768], sQ[768], sK[768], sV[768];
  __shared__ float sAtt[576];
  __shared__ float sX1[768];
  __shared__ float sH[3072];
  __shared__ float sR[3072];

  int tid = threadIdx.x;
  long base = (long)blockIdx.x * 768;

  const float* Wq_  = Wq  + l*4096;
  const float* Wk_  = Wk  + l*4096;
  const float* Wv_  = Wv  + l*4096;
  const float* Wo_  = Wo  + l*4096;
  const float* bo_  = bo  + l*64;
  const float* ln1g_= ln1g+ l*64;  const float* ln1b_= ln1b+ l*64;
  const float* ln2g_= ln2g+ l*64;  const float* ln2b_= ln2b+ l*64;
  const float* fw1_ = fw1 + l*16384; const float* fb1_ = fb1 + l*256;
  const float* fw2_ = fw2 + l*16384; const float* fb2_ = fb2 + l*64;
  const float* lng_ = lng + l*64;  const float* lnb_ = lnb + l*64;

  for (int idx=tid; idx<768; idx+=256){
    float tv = temb[idx];
    sT[idx]  = tv;
    sQQ[idx] = g_out[base+idx] + tv;
  }
  __syncthreads();

  // ---- Q,K,V = qq @ W (64-col thread per matrix; W read once per block) ----
  if (tid < 192){
    int g = tid >> 6, e = tid & 63;
    const float* W = (g==0 ? Wq_ : (g==1 ? Wk_ : Wv_)) + e;
    float* dst = (g==0 ? sQ : (g==1 ? sK : sV)) + e;
    float acc[12];
    #pragma unroll
    for (int t2=0;t2<12;t2++) acc[t2]=0.f;
    const float4* q4 = (const float4*)sQQ;
    #pragma unroll 4
    for (int k4=0;k4<16;k4++){
      float w0 = W[(4*k4+0)*64];
      float w1v= W[(4*k4+1)*64];
      float w2v= W[(4*k4+2)*64];
      float w3v= W[(4*k4+3)*64];
      #pragma unroll
      for (int t2=0;t2<12;t2++){
        float4 q = q4[t2*16 + k4];
        acc[t2] += q.x*w0 + q.y*w1v + q.z*w2v + q.w*w3v;
      }
    }
    #pragma unroll
    for (int t2=0;t2<12;t2++) dst[t2*64] = acc[t2];
  }
  __syncthreads();

  // ---- attention scores ----
  for (int idx=tid; idx<576; idx+=256){
    int h = idx/144, rem = idx - h*144;
    int t2 = rem/12, s = rem - t2*12;
    const float* qp = sQ + t2*64 + h*16;
    const float* kp = sK + s*64 + h*16;
    float sum=0.f;
    #pragma unroll
    for (int dd=0;dd<16;dd++) sum += qp[dd]*kp[dd];
    sAtt[idx] = sum*0.25f;   // scale = 1/sqrt(16)
  }
  __syncthreads();
  if (tid < 48){
    float* row = sAtt + tid*12;
    float mx = row[0];
    #pragma unroll
    for (int s=1;s<12;s++) mx = fmaxf(mx,row[s]);
    float ev[12]; float sum=0.f;
    #pragma unroll
    for (int s=0;s<12;s++){ ev[s]=__expf(row[s]-mx); sum+=ev[s]; }
    float inv = 1.f/sum;
    #pragma unroll
    for (int s=0;s<12;s++) row[s]=ev[s]*inv;
  }
  __syncthreads();

  // ---- ctx = att @ V  (write into sQ, Q no longer needed) ----
  for (int idx=tid; idx<768; idx+=256){
    int t2 = idx>>6, e = idx&63, h = e>>4;
    const float* a = sAtt + (h*12+t2)*12;
    float sum=0.f;
    #pragma unroll
    for (int s=0;s<12;s++) sum += a[s]*sV[s*64+e];
    sQ[idx] = sum;
  }
  __syncthreads();

  // ---- attn_out = ctx @ Wo (k-split by 4 groups) ----
  {
    int kg = tid>>6, e = tid&63;
    const float* W = Wo_ + e;
    float acc[12];
    #pragma unroll
    for (int t2=0;t2<12;t2++) acc[t2]=0.f;
    const float4* c4 = (const float4*)sQ;
    #pragma unroll
    for (int j=0;j<4;j++){
      int k = kg*16 + 4*j;
      float w0 = W[(k+0)*64], w1v = W[(k+1)*64], w2v = W[(k+2)*64], w3v = W[(k+3)*64];
      #pragma unroll
      for (int t2=0;t2<12;t2++){
        float4 q = c4[t2*16 + kg*4 + j];
        acc[t2] += q.x*w0 + q.y*w1v + q.z*w2v + q.w*w3v;
      }
    }
    #pragma unroll
    for (int t2=0;t2<12;t2++) sR[kg*768 + t2*64 + e] = acc[t2];
  }
  __syncthreads();
  for (int idx=tid; idx<768; idx+=256){
    int e = idx&63;
    sX1[idx] = sR[idx]+sR[768+idx]+sR[1536+idx]+sR[2304+idx] + bo_[e] + sQQ[idx];
  }
  __syncthreads();
  ln_rows(sX1, ln1g_, ln1b_, sX1);
  __syncthreads();

  // ---- FF1: h = relu(x1 @ fw1 + b1), 256 cols ----
  {
    int f = tid;
    float acc[12];
    #pragma unroll
    for (int t2=0;t2<12;t2++) acc[t2]=0.f;
    const float4* x4 = (const float4*)sX1;
    #pragma unroll 4
    for (int k4=0;k4<16;k4++){
      float w0 = fw1_[(4*k4+0)*256 + f];
      float w1v= fw1_[(4*k4+1)*256 + f];
      float w2v= fw1_[(4*k4+2)*256 + f];
      float w3v= fw1_[(4*k4+3)*256 + f];
      #pragma unroll
      for (int t2=0;t2<12;t2++){
        float4 q = x4[t2*16 + k4];
        acc[t2] += q.x*w0 + q.y*w1v + q.z*w2v + q.w*w3v;
      }
    }
    float bb = fb1_[f];
    #pragma unroll
    for (int t2=0;t2<12;t2++) sH[t2*256+f] = fmaxf(acc[t2]+bb, 0.f);
  }
  __syncthreads();

  // ---- FF2: k-split by 4 groups over 256 ----
  {
    int kg = tid>>6, e = tid&63;
    float acc[12];
    #pragma unroll
    for (int t2=0;t2<12;t2++) acc[t2]=0.f;
    const float4* h4 = (const float4*)sH;
    #pragma unroll 4
    for (int k4=kg*16; k4<kg*16+16; k4++){
      int k = 4*k4;
      float w0 = fw2_[(k+0)*64+e], w1v = fw2_[(k+1)*64+e];
      float w2v= fw2_[(k+2)*64+e], w3v = fw2_[(k+3)*64+e];
      #pragma unroll
      for (int t2=0;t2<12;t2++){
        float4 q = h4[t2*64 + k4];
        acc[t2] += q.x*w0 + q.y*w1v + q.z*w2v + q.w*w3v;
      }
    }
    #pragma unroll
    for (int t2=0;t2<12;t2++) sR[kg*768 + t2*64 + e] = acc[t2];
  }
  __syncthreads();
  for (int idx=tid; idx<768; idx+=256){
    int e = idx&63;
    sK[idx] = sR[idx]+sR[768+idx]+sR[1536+idx]+sR[2304+idx] + fb2_[e] + sX1[idx];
  }
  __syncthreads();
  ln_rows(sK, ln2g_, ln2b_, sK);
  __syncthreads();
  // out = LN(blk + out_prev), out_prev = qq - temb
  for (int idx=tid; idx<768; idx+=256)
    sV[idx] = sK[idx] + sQQ[idx] - sT[idx];
  __syncthreads();
  ln_rows(sV, lng_, lnb_, g_out + base);
}

// ---------------------------------------------------------------------------
// K3: conv2 (temporal) + relu + conv3 head. One warp per (b,n).
// ---------------------------------------------------------------------------
__global__ void __launch_bounds__(128) k_final(
    const float* __restrict__ w2, const float* __restrict__ b2,
    const float* __restrict__ w3, const float* __restrict__ b3,
    float* __restrict__ outp)
{
  int id = blockIdx.x*4 + (threadIdx.x>>5);
  if (id >= BB*NV) return;
  int lane = threadIdx.x & 31;
  const float* row = g_out + (long)id*768;
  float o0[12], o1[12];
  #pragma unroll
  for (int t=0;t<12;t++){ o0[t]=row[t*64+lane]; o1[t]=row[t*64+lane+32]; }
  float w3a = w3[lane], w3b = w3[lane+32];
  float b3v = b3[0];
  #pragma unroll
  for (int o=0;o<12;o++){
    float v0 = b2[o], v1 = b2[o];
    #pragma unroll
    for (int t=0;t<12;t++){ float w = w2[o*12+t]; v0 += o0[t]*w; v1 += o1[t]*w; }
    v0 = fmaxf(v0,0.f); v1 = fmaxf(v1,0.f);
    float p = warp_sum(v0*w3a + v1*w3b);
    if (lane==0) outp[id*12+o] = p + b3v;
  }
}

// ---------------------------------------------------------------------------
extern "C" void kernel_launch(void* const* d_in, const int* in_sizes, int n_in,
                              void* d_out, int out_size) {
  const float* x       = (const float*)d_in[0];
  const int*   adj     = (const int*)  d_in[1];
  const float* gat_W2  = (const float*)d_in[2];
  const float* gat_a   = (const float*)d_in[3];
  const float* gat_b   = (const float*)d_in[4];
  const float* conv1_w = (const float*)d_in[5];
  const float* conv1_b = (const float*)d_in[6];
  const float* temb    = (const float*)d_in[7];
  const float* Wq      = (const float*)d_in[8];
  const float* Wk      = (const float*)d_in[9];
  const float* Wv      = (const float*)d_in[10];
  const float* Wo      = (const float*)d_in[11];
  const float* bo      = (const float*)d_in[12];
  const float* ln1_g   = (const float*)d_in[13];
  const float* ln1_b   = (const float*)d_in[14];
  const float* ln2_g   = (const float*)d_in[15];
  const float* ln2_b   = (const float*)d_in[16];
  const float* ff_w1   = (const float*)d_in[17];
  const float* ff_b1   = (const float*)d_in[18];
  const float* ff_w2   = (const float*)d_in[19];
  const float* ff_b2   = (const float*)d_in[20];
  const float* lng     = (const float*)d_in[21];
  const float* lnb     = (const float*)d_in[22];
  const float* conv2_w = (const float*)d_in[23];
  const float* conv2_b = (const float*)d_in[24];
  const float* conv3_w = (const float*)d_in[25];
  const float* conv3_b = (const float*)d_in[26];
  float* outp = (float*)d_out;

  dim3 g1(BB*TT, (NV + 3) / 4);
  k_gat<<<g1, 128>>>(x, adj, gat_W2, gat_a, gat_b, conv1_w, conv1_b);

  for (int l = 0; l < LL; l++) {
    k_layer<<<BB*NV, 256>>>(temb, Wq, Wk, Wv, Wo, bo,
                            ln1_g, ln1_b, ln2_g, ln2_b,
                            ff_w1, ff_b1, ff_w2, ff_b2,
                            lng, lnb, l);
  }

  k_final<<<(BB*NV + 3)/4, 128>>>(conv2_w, conv2_b, conv3_w, conv3_b, outp);
}